// round 1
// baseline (speedup 1.0000x reference)
#include <cuda_runtime.h>

#define N_NODES 131072
#define N_EDGES 2097152
#define N_GRAPHS 64
#define NODES_PER_GRAPH 2048
#define D_IN 128
#define D_EMB 64
#define D_HID 128
#define N_ACT 2048

// ---------------- scratch (device globals, 16B aligned via float4) ----------
__device__ float4 g_zl4 [N_NODES * D_EMB / 4];   // x @ Wl.T   (messages to aggregate)
__device__ float4 g_zr4 [N_NODES * D_EMB / 4];   // x @ Wr.T   (self term)
__device__ float4 g_agg4[N_NODES * D_EMB / 4];   // segment-sum target
__device__ float4 g_h4  [N_NODES * D_EMB / 4];   // h1 then h2
__device__ float  g_cnt [N_NODES];               // in-degree (computed once, reused)
__device__ float  g_pool[N_GRAPHS * D_EMB];

#define G_ZL  ((float*)g_zl4)
#define G_ZR  ((float*)g_zr4)
#define G_AGG ((float*)g_agg4)
#define G_H   ((float*)g_h4)

// ---------------- zero agg (+cnt on first layer) ----------------------------
__global__ void zero_kernel(int zero_cnt) {
    int idx    = blockIdx.x * blockDim.x + threadIdx.x;
    int stride = gridDim.x * blockDim.x;
    float4 z = make_float4(0.f, 0.f, 0.f, 0.f);
    for (int j = idx; j < N_NODES * D_EMB / 4; j += stride) g_agg4[j] = z;
    if (zero_cnt)
        for (int j = idx; j < N_NODES; j += stride) g_cnt[j] = 0.f;
}

// ---------------- fused dual projection: zl = in@Wl.T, zr = in@Wr.T ---------
// Block computes a 64-node x 128-output tile (outputs 0..63 -> zl, 64..127 -> zr).
// 256 threads as 16x16, each thread owns a 4x8 register micro-tile.
template <int K>
__global__ void lin_kernel(const float* __restrict__ in_param,
                           const float* __restrict__ Wl,
                           const float* __restrict__ Wr) {
    extern __shared__ float sm[];
    float* xs = sm;             // [64][K]
    float* Wt = sm + 64 * K;    // [K][129]  (padded row to kill bank conflicts)

    const float* in = (K == D_EMB) ? G_H : in_param;   // layer 2 reads h1 symbol

    const int tid = threadIdx.x;
    const int n0  = blockIdx.x * 64;

    // Load weights transposed into shared: Wt[k][o] (o<64: Wl, o>=64: Wr)
    for (int idx = tid; idx < 64 * K; idx += 256) {
        int k = idx % K, o = idx / K;          // coalesced reads over k
        Wt[k * 129 + o]      = Wl[o * K + k];
        Wt[k * 129 + 64 + o] = Wr[o * K + k];
    }
    // Load 64 input rows (vectorized)
    const float4* inv = (const float4*)(in + (size_t)n0 * K);
    float4* xsv = (float4*)xs;
    for (int idx = tid; idx < 64 * K / 4; idx += 256) xsv[idx] = inv[idx];
    __syncthreads();

    const int tr = tid >> 4;      // 0..15 (node group)
    const int tc = tid & 15;      // 0..15 (output group)

    float acc[4][8];
#pragma unroll
    for (int a = 0; a < 4; a++)
#pragma unroll
        for (int b = 0; b < 8; b++) acc[a][b] = 0.f;

#pragma unroll 4
    for (int k = 0; k < K; k++) {
        float xv[4], wv[8];
#pragma unroll
        for (int a = 0; a < 4; a++) xv[a] = xs[(tr + 16 * a) * K + k];
#pragma unroll
        for (int b = 0; b < 8; b++) wv[b] = Wt[k * 129 + tc + 16 * b];
#pragma unroll
        for (int a = 0; a < 4; a++)
#pragma unroll
            for (int b = 0; b < 8; b++) acc[a][b] += xv[a] * wv[b];
    }

#pragma unroll
    for (int a = 0; a < 4; a++) {
        size_t n = (size_t)(n0 + tr + 16 * a);
#pragma unroll
        for (int b = 0; b < 4; b++)
            G_ZL[n * D_EMB + tc + 16 * b] = acc[a][b];
#pragma unroll
        for (int b = 4; b < 8; b++)
            G_ZR[n * D_EMB + tc + 16 * (b - 4)] = acc[a][b];
    }
}

// ---------------- edge aggregation: agg[dst] += zl[src] ---------------------
// One warp per edge (looped). Messages are 64 floats; lanes cover 2x32.
__global__ void agg_kernel(const int* __restrict__ src,
                           const int* __restrict__ dst,
                           int add_cnt) {
    const int lane    = threadIdx.x & 31;
    const int warp_id = (blockIdx.x * blockDim.x + threadIdx.x) >> 5;
    const int nwarps  = (gridDim.x * blockDim.x) >> 5;

    for (int e = warp_id; e < N_EDGES; e += nwarps) {
        int s = __ldg(&src[e]);
        int d = __ldg(&dst[e]);
        const float* zs = G_ZL + (size_t)s * D_EMB;
        float*       ad = G_AGG + (size_t)d * D_EMB;
        atomicAdd(ad + lane,      __ldg(zs + lane));
        atomicAdd(ad + 32 + lane, __ldg(zs + 32 + lane));
        if (add_cnt && lane == 0) atomicAdd(&g_cnt[d], 1.0f);
    }
}

// ---------------- h = agg/max(cnt,1) + b + zr --------------------------------
__global__ void h_kernel(const float* __restrict__ b) {
    int i = blockIdx.x * blockDim.x + threadIdx.x;   // over N_NODES*64
    int node = i >> 6, o = i & 63;
    float c = fmaxf(g_cnt[node], 1.0f);
    G_H[i] = G_AGG[i] / c + __ldg(&b[o]) + G_ZR[i];
}

// ---------------- graph mean pool: g_pool[g][d] = mean over 2048 nodes ------
__global__ void pool_kernel() {
    __shared__ float red[256];
    const int g = blockIdx.x, tid = threadIdx.x;
    const int d = tid & 63, part = tid >> 6;
    const float* base = G_H + (size_t)g * NODES_PER_GRAPH * D_EMB;
    float s = 0.f;
    for (int n = part; n < NODES_PER_GRAPH; n += 4)
        s += base[n * D_EMB + d];
    red[tid] = s;
    __syncthreads();
    if (part == 0) {
        float t = red[d] + red[64 + d] + red[128 + d] + red[192 + d];
        g_pool[g * D_EMB + d] = t * (1.0f / NODES_PER_GRAPH);
    }
}

// ---------------- MLP head: q = relu(g@fc1.T+b1)@fc2.T + b2 -----------------
__global__ void head_kernel(const float* __restrict__ fc1_W,
                            const float* __restrict__ fc1_b,
                            const float* __restrict__ fc2_W,
                            const float* __restrict__ fc2_b,
                            float* __restrict__ out) {
    __shared__ float gs[D_EMB];
    __shared__ float hs[D_HID];
    const int g = blockIdx.x, tid = threadIdx.x;
    if (tid < D_EMB) gs[tid] = g_pool[g * D_EMB + tid];
    __syncthreads();
    if (tid < D_HID) {
        float acc = fc1_b[tid];
        const float* w = fc1_W + (size_t)tid * D_EMB;
#pragma unroll
        for (int k = 0; k < D_EMB; k++) acc += gs[k] * w[k];
        hs[tid] = fmaxf(acc, 0.f);
    }
    __syncthreads();
    for (int a = tid; a < N_ACT; a += 256) {
        const float4* w = (const float4*)(fc2_W + (size_t)a * D_HID);
        float a0 = 0.f, a1 = 0.f, a2 = 0.f, a3 = 0.f;
#pragma unroll
        for (int k = 0; k < D_HID / 4; k++) {
            float4 wv = __ldg(&w[k]);
            a0 += wv.x * hs[4 * k + 0];
            a1 += wv.y * hs[4 * k + 1];
            a2 += wv.z * hs[4 * k + 2];
            a3 += wv.w * hs[4 * k + 3];
        }
        out[(size_t)g * N_ACT + a] = fc2_b[a] + (a0 + a1) + (a2 + a3);
    }
}

// ---------------- launch ------------------------------------------------------
extern "C" void kernel_launch(void* const* d_in, const int* in_sizes, int n_in,
                              void* d_out, int out_size) {
    const float* x     = (const float*)d_in[0];
    const int*   ei    = (const int*)d_in[1];
    const float* W1l   = (const float*)d_in[2];
    const float* b1l   = (const float*)d_in[3];
    const float* W1r   = (const float*)d_in[4];
    const float* W2l   = (const float*)d_in[5];
    const float* b2l   = (const float*)d_in[6];
    const float* W2r   = (const float*)d_in[7];
    const float* fc1_W = (const float*)d_in[8];
    const float* fc1_b = (const float*)d_in[9];
    const float* fc2_W = (const float*)d_in[10];
    const float* fc2_b = (const float*)d_in[11];
    float* out = (float*)d_out;

    const int* src = ei;
    const int* dst = ei + N_EDGES;

    const int SMEM128 = (64 * D_IN + D_IN * 129) * 4;   // 98816 B
    const int SMEM64  = (64 * D_EMB + D_EMB * 129) * 4; // 49408 B
    cudaFuncSetAttribute(lin_kernel<D_IN>,  cudaFuncAttributeMaxDynamicSharedMemorySize, SMEM128);
    cudaFuncSetAttribute(lin_kernel<D_EMB>, cudaFuncAttributeMaxDynamicSharedMemorySize, SMEM64);

    // ---- layer 1 ----
    zero_kernel<<<2048, 256>>>(1);
    lin_kernel<D_IN><<<N_NODES / 64, 256, SMEM128>>>(x, W1l, W1r);
    agg_kernel<<<2048, 256>>>(src, dst, 1);
    h_kernel<<<N_NODES * D_EMB / 256, 256>>>(b1l);

    // ---- layer 2 (cnt reused) ----
    zero_kernel<<<2048, 256>>>(0);
    lin_kernel<D_EMB><<<N_NODES / 64, 256, SMEM64>>>(nullptr, W2l, W2r);
    agg_kernel<<<2048, 256>>>(src, dst, 0);
    h_kernel<<<N_NODES * D_EMB / 256, 256>>>(b2l);

    // ---- pool + head ----
    pool_kernel<<<N_GRAPHS, 256>>>();
    head_kernel<<<N_GRAPHS, 256>>>(fc1_W, fc1_b, fc2_W, fc2_b, out);
}